// round 15
// baseline (speedup 1.0000x reference)
#include <cuda_runtime.h>
#include <cuda_fp16.h>
#include <cstdint>

// out[t,s] = sum_{k<=t} sum_a A[k,s,a] * us[t-k,a]
// GEMM: C[s,t] = sum_{k,a} A[k,s,a] * Upad[t+128-k, a]
// mma.sync.m16n8k16, single fp16 chain (rel_err ~2.7e-4 measured).
// R15: warp-specialized producer/consumer. R11-R14 all show tensor~33%,
// issue~34%, nothing saturated -> the per-iter barrier convoy (every
// thread loads AND computes) is the suspected serializer.
//  - 384 threads: 8 consumer warps (LDSM+MMA only, R11 fragment
//    geometry) + 4 producer warps (one per SMSP: LDG A fp32 -> cvt ->
//    STS fp16, cp.async B).
//  - 4-stage 24KB ring, mbarrier full[s] (256: 128 cp.async-arrives +
//    128 STS-arrives) / free[s] (8: one lane per consumer warp).
//    Zero __syncthreads in the mainloop.
//  - Work split identical to R11: 16 s-tiles x KSPLIT=18 = 288 CTAs,
//    occ 2, balanced reflected k-sets -> same accumulation order.
// Deterministic split-K partials + reduce. Dummies keep ncu on mma.

#define KSPLIT 18
#define NSTAGE 4
#define ASIZE  8192           // A: 64 rows x 128 B fp16
#define BSIZE  16384          // B: 128 rows x 128 B fp16
#define STGSZ  (ASIZE + BSIZE)
#define SMEMT  (NSTAGE * STGSZ)      // 98304 B

__device__ float  g_partial[KSPLIT*128*1024];
__device__ __half g_Uf[256*512];

__global__ __launch_bounds__(256) void prep_kernel(const float* __restrict__ us)
{
    int i = blockIdx.x*256 + threadIdx.x;
    int r = i >> 9, a = i & 511;
    float x = (r >= 128) ? us[(r-128)*512 + a] : 0.f;
    g_Uf[i] = __float2half_rn(x);
}

__global__ void dummy_kernel() {}

__device__ __forceinline__ void ldmx4(uint32_t* r, uint32_t addr) {
    asm volatile("ldmatrix.sync.aligned.m8n8.x4.shared.b16 {%0,%1,%2,%3}, [%4];"
        : "=r"(r[0]), "=r"(r[1]), "=r"(r[2]), "=r"(r[3]) : "r"(addr));
}
__device__ __forceinline__ void mma16816(float* c, const uint32_t* a, const uint32_t* b) {
    asm volatile("mma.sync.aligned.m16n8k16.row.col.f32.f16.f16.f32 "
        "{%0,%1,%2,%3}, {%4,%5,%6,%7}, {%8,%9}, {%0,%1,%2,%3};"
        : "+f"(c[0]), "+f"(c[1]), "+f"(c[2]), "+f"(c[3])
        : "r"(a[0]), "r"(a[1]), "r"(a[2]), "r"(a[3]), "r"(b[0]), "r"(b[1]));
}
__device__ __forceinline__ void cpa16(uint32_t dst, const void* src) {
    asm volatile("cp.async.cg.shared.global [%0], [%1], 16;" :: "r"(dst), "l"(src));
}
__device__ __forceinline__ uint32_t packh(float a, float b) {
    __half2 h = __floats2half2_rn(a, b);
    return *reinterpret_cast<uint32_t*>(&h);
}
__device__ __forceinline__ void mbar_wait(uint32_t mbar, uint32_t parity) {
    asm volatile(
        "{\n\t.reg .pred P;\n"
        "LAB_%=:\n\t"
        "mbarrier.try_wait.parity.acquire.cta.shared::cta.b64 P, [%0], %1, 0x989680;\n\t"
        "@!P bra LAB_%=;\n\t}"
        :: "r"(mbar), "r"(parity) : "memory");
}
__device__ __forceinline__ void mbar_arrive(uint32_t mbar) {
    asm volatile("mbarrier.arrive.shared.b64 _, [%0];" :: "r"(mbar) : "memory");
}
__device__ __forceinline__ void cp_mbar_arrive(uint32_t mbar) {
    asm volatile("cp.async.mbarrier.arrive.noinc.shared.b64 [%0];" :: "r"(mbar) : "memory");
}

// k-set for group g (0..17) — identical to R11 (same accumulation order)
__device__ __forceinline__ void kofit(int g, int i, int& k, int& a0) {
    const int t = i >> 3;
    if (t == 7)      k = 143 - g;
    else if (t & 1)  k = 36*((t+1) >> 1) - 1 - g;
    else             k = 36*(t >> 1) + g;
    a0 = (i & 7) << 6;
}

__global__ __launch_bounds__(384, 2)
void mma_kernel(const float* __restrict__ A)
{
    extern __shared__ char smem[];
    __shared__ __align__(8) uint64_t mbar_store[2*NSTAGE];
    const uint32_t smb = (uint32_t)__cvta_generic_to_shared(smem);
    const uint32_t mb0 = (uint32_t)__cvta_generic_to_shared(mbar_store);
    // full[s] at mb0 + s*8 ; free[s] at mb0 + 32 + s*8

    const int tid = threadIdx.x;
    const int s0  = blockIdx.x * 64;
    const int g   = blockIdx.y;
    const int NIT = (g >= 16) ? 64 : 56;

    if (tid == 0) {
        for (int s = 0; s < NSTAGE; s++) {
            asm volatile("mbarrier.init.shared.b64 [%0], %1;"
                         :: "r"(mb0 + s*8), "r"(256u) : "memory");
            asm volatile("mbarrier.init.shared.b64 [%0], %1;"
                         :: "r"(mb0 + 32 + s*8), "r"(8u) : "memory");
        }
    }
    __syncthreads();

    if (tid < 256) {
        // ================= consumers: LDSM + MMA only =================
        const int wid  = tid >> 5;
        const int lane = tid & 31;
        const int wm   = wid >> 2;                    // 2 m-groups
        const int ng   = (wid < 4) ? wid : 7 - wid;   // SMSP-balanced

        const int arow  = wm*32 + (lane & 15);
        const int axor  = arow & 7;
        const int asel  = lane >> 4;
        const int browl = 8*ng + (lane & 7) + 32*((lane >> 4) & 1);
        const int bxor  = lane & 7;
        const int bsel  = (lane >> 3) & 1;

        float acc[2][4][4];
#pragma unroll
        for (int im = 0; im < 2; im++)
#pragma unroll
            for (int j = 0; j < 4; j++)
#pragma unroll
                for (int c = 0; c < 4; c++) acc[im][j][c] = 0.f;

        for (int it = 0; it < NIT; it++) {
            const int s = it & 3, f = it >> 2;
            mbar_wait(mb0 + s*8, f & 1);

            int k, a0d; kofit(g, it, k, a0d);
            bool lv[4];
#pragma unroll
            for (int j = 0; j < 4; j++)
                lv[j] = (k < ((4*j + ng) << 3) + 8);
            bool lp[2];
#pragma unroll
            for (int p = 0; p < 2; p++)
                lp[p] = lv[2*p + 1];

            const uint32_t ab = smb + s*STGSZ + arow*128;
            const uint32_t bb = smb + s*STGSZ + ASIZE + browl*128;
#pragma unroll
            for (int kb = 0; kb < 4; kb++) {
                uint32_t ah[2][4], uf[2][4];
                const int au = 2*kb + asel;
                ldmx4(ah[0], ab +        ((au ^ axor) << 4));
                ldmx4(ah[1], ab + 2048 + ((au ^ axor) << 4));
                const int bu = 2*kb + bsel;
                const uint32_t bsw = (uint32_t)((bu ^ bxor) << 4);
#pragma unroll
                for (int p = 0; p < 2; p++)
                    if (lp[p]) ldmx4(uf[p], bb + p*8192 + bsw);
#pragma unroll
                for (int im = 0; im < 2; im++)
#pragma unroll
                    for (int j = 0; j < 4; j++)
                        if (lv[j])
                            mma16816(acc[im][j], ah[im], &uf[j >> 1][(j & 1) * 2]);
            }

            if (lane == 0) mbar_arrive(mb0 + 32 + s*8);
        }

        // epilogue: split-K partials [g][t][s]
        float* pb = g_partial + (size_t)g * 131072;
        const int sidx = s0 + wm*32 + (lane >> 2);
#pragma unroll
        for (int im = 0; im < 2; im++) {
            const int sr = sidx + im*16;
#pragma unroll
            for (int j = 0; j < 4; j++) {
                const int n = ((4*j + ng) << 3) + (lane & 3) * 2;
                pb[(size_t)n      * 1024 + sr]     = acc[im][j][0];
                pb[(size_t)(n+1)  * 1024 + sr]     = acc[im][j][1];
                pb[(size_t)n      * 1024 + sr + 8] = acc[im][j][2];
                pb[(size_t)(n+1)  * 1024 + sr + 8] = acc[im][j][3];
            }
        }
    } else {
        // ================= producers: LDG/cvt/STS A + cp.async B =======
        const int ptid   = tid - 256;      // 0..127
        const int arow_p = ptid >> 1;      // 0..63 (A row)
        const int ahalf  = ptid & 1;       // which 32-float half
        const int brow_p = ptid;           // 0..127 (B row)
        const int brx    = brow_p & 7;
        const int arx    = arow_p & 7;

        float rF[32];

        auto ldgA = [&](int k, int a0) {
            const float* p = A + ((size_t)k*1024 + s0 + arow_p)*512 + a0 + ahalf*32;
#pragma unroll
            for (int c = 0; c < 8; c++) {
                float4 v = *reinterpret_cast<const float4*>(p + c*4);
                rF[4*c+0] = v.x; rF[4*c+1] = v.y; rF[4*c+2] = v.z; rF[4*c+3] = v.w;
            }
        };
        auto cvtstsA = [&](int s) {
            char* base = smem + s*STGSZ + arow_p*128;
#pragma unroll
            for (int c = 0; c < 4; c++) {
                uint4 w = make_uint4(packh(rF[8*c+0], rF[8*c+1]),
                                     packh(rF[8*c+2], rF[8*c+3]),
                                     packh(rF[8*c+4], rF[8*c+5]),
                                     packh(rF[8*c+6], rF[8*c+7]));
                const int u = ahalf*4 + c;
                *reinterpret_cast<uint4*>(base + ((u ^ arx) << 4)) = w;
            }
        };
        auto cpB = [&](int k, int a0, int s) {
            const __half* src = g_Uf + (size_t)(brow_p + 128 - k)*512 + a0;
            const uint32_t dst = smb + s*STGSZ + ASIZE + brow_p*128;
#pragma unroll
            for (int u = 0; u < 8; u++)
                cpa16(dst + ((u ^ brx) << 4), src + u*8);
        };

        { int k, a0; kofit(g, 0, k, a0); ldgA(k, a0); }

        for (int it = 0; it < NIT; it++) {
            const int s = it & 3, f = it >> 2;
            if (f >= 1) mbar_wait(mb0 + 32 + s*8, (f - 1) & 1);

            int k, a0; kofit(g, it, k, a0);
            cpB(k, a0, s);
            cp_mbar_arrive(mb0 + s*8);       // arrives when this thread's cp.asyncs land
            cvtstsA(s);
            mbar_arrive(mb0 + s*8);          // release: STS visible to consumers

            if (it + 1 < NIT) {
                int kn, a0n; kofit(g, it + 1, kn, a0n);
                ldgA(kn, a0n);               // latency spans the next wait/cpB
            }
        }
    }
}

__global__ __launch_bounds__(256) void reduce_kernel(float* __restrict__ out)
{
    int i = blockIdx.x*256 + threadIdx.x;
    float s = 0.f;
#pragma unroll
    for (int gg = 0; gg < KSPLIT; gg++)
        s += g_partial[(size_t)gg*131072 + i];
    out[i] = s;
}

extern "C" void kernel_launch(void* const* d_in, const int* in_sizes, int n_in,
                              void* d_out, int out_size)
{
    const float* us = (const float*)d_in[0];   // [128, 512]
    const float* A  = (const float*)d_in[1];   // [128, 1024, 512]
    if (n_in >= 2 && in_sizes[0] > in_sizes[1]) {
        const float* t = us; us = A; A = t;
    }
    cudaFuncSetAttribute(mma_kernel, cudaFuncAttributeMaxDynamicSharedMemorySize, SMEMT);

    prep_kernel<<<512, 256>>>(us);
    dummy_kernel<<<1, 1>>>();
    dummy_kernel<<<1, 1>>>();
    mma_kernel<<<dim3(16, KSPLIT), 384, SMEMT>>>(A);
    reduce_kernel<<<512, 256>>>((float*)d_out);
}

// round 16
// speedup vs baseline: 1.5554x; 1.5554x over previous
#include <cuda_runtime.h>
#include <cuda_fp16.h>
#include <cstdint>

// out[t,s] = sum_{k<=t} sum_a A[k,s,a] * us[t-k,a]
// GEMM: C[s,t] = sum_{k,a} A[k,s,a] * Upad[t+128-k, a]
// mma.sync.m16n8k16, single fp16 chain (rel_err ~2.7e-4 measured).
// R16: R11's proven body (92.6us best; R12-R15 restructures all
// regressed) + fixed schedule. R11's k-sets gave g>=16 64 iters vs 56
// (+14% tail; fixed per-iter overhead dominates, so iter COUNT sets
// CTA time). New uniform-quanta schedule: q in [0,1024) per s-tile,
// p=q>>4, k=(q&1)?127-p:p, a0=((q>>1)&7)<<6 (reflected pairs = const
// live cost); CTA g takes q in [g*1024/18,(g+1)*1024/18) -> 56-57
// iters (+-1.8%). Also: hoisted (k,a0), float4 reduce.
// Occ 2, 16 s-tiles x KSPLIT=18 = 288 CTAs, CTA 64m x 128n, 8 warps
// (2m x 4n interleaved n8 tiles, SMSP-balanced ng), causal skip on
// MMA + B ldmatrix, K=64/iter, deferred-convert A pipeline, triple-
// buffered B cp.async, XOR-swizzled 128B rows. Deterministic split-K
// partials + reduce. Dummies keep ncu's capture slot on mma_kernel.

#define KSPLIT 18
#define ATILE  8192           // 64 rows x 128 B
#define BTILE  16384          // 128 rows x 128 B
#define BOFF0  (2*ATILE)
#define SMEMT  (2*ATILE + 3*BTILE)   // 65536 B

__device__ float  g_partial[KSPLIT*128*1024];  // 9.4 MB
__device__ __half g_Uf[256*512];

__global__ __launch_bounds__(256) void prep_kernel(const float* __restrict__ us)
{
    int i = blockIdx.x*256 + threadIdx.x;   // 0..131071 over [256][512]
    int r = i >> 9, a = i & 511;
    float x = (r >= 128) ? us[(r-128)*512 + a] : 0.f;
    g_Uf[i] = __float2half_rn(x);
}

__global__ void dummy_kernel() {}

__device__ __forceinline__ void ldmx4(uint32_t* r, uint32_t addr) {
    asm volatile("ldmatrix.sync.aligned.m8n8.x4.shared.b16 {%0,%1,%2,%3}, [%4];"
        : "=r"(r[0]), "=r"(r[1]), "=r"(r[2]), "=r"(r[3]) : "r"(addr));
}
__device__ __forceinline__ void mma16816(float* c, const uint32_t* a, const uint32_t* b) {
    asm volatile("mma.sync.aligned.m16n8k16.row.col.f32.f16.f16.f32 "
        "{%0,%1,%2,%3}, {%4,%5,%6,%7}, {%8,%9}, {%0,%1,%2,%3};"
        : "+f"(c[0]), "+f"(c[1]), "+f"(c[2]), "+f"(c[3])
        : "r"(a[0]), "r"(a[1]), "r"(a[2]), "r"(a[3]), "r"(b[0]), "r"(b[1]));
}
__device__ __forceinline__ void cpa16(uint32_t dst, const void* src) {
    asm volatile("cp.async.cg.shared.global [%0], [%1], 16;" :: "r"(dst), "l"(src));
}
__device__ __forceinline__ uint32_t packh(float a, float b) {
    __half2 h = __floats2half2_rn(a, b);
    return *reinterpret_cast<uint32_t*>(&h);
}

__global__ __launch_bounds__(256, 2)
void mma_kernel(const float* __restrict__ A)
{
    extern __shared__ char smem[];
    const uint32_t smb = (uint32_t)__cvta_generic_to_shared(smem);

    const int tid  = threadIdx.x;
    const int wid  = tid >> 5;
    const int lane = tid & 31;
    const int wm   = wid >> 2;                     // 2 m-groups of 32
    const int ng   = (wid < 4) ? wid : 7 - wid;    // SMSP-balanced n-group
    const int s0   = blockIdx.x * 64;
    const int g    = blockIdx.y;

    // uniform-cost quanta: q -> p=q>>4, k=(q&1)?127-p:p, a=(q>>1)&7
    const int qs  = (g * 1024) / KSPLIT;
    const int qe  = ((g + 1) * 1024) / KSPLIT;
    const int NIT = qe - qs;                       // 56 or 57

    auto kofit = [&](int it, int& k, int& a0) {
        const int q = qs + it;
        const int p = q >> 4;
        k  = (q & 1) ? (127 - p) : p;
        a0 = ((q >> 1) & 7) << 6;
    };

    // A loader: 16 threads/row, rows rowgrp+16*jj (jj 0..3)
    const int rowgrp = tid >> 4;        // 0..15
    const int lane16 = tid & 15;
    // B loader: 2 threads per row
    const int brow  = tid >> 1;         // 0..127
    const int bhalf = tid & 1;

    // ldmatrix geometry (16B-unit XOR swizzle on 128B rows)
    const int arow  = wm*32 + (lane & 15);                        // 0..63
    const int axor  = arow & 7;
    const int asel  = lane >> 4;
    const int browl = 8*ng + (lane & 7) + 32*((lane >> 4) & 1);   // 0..127
    const int bxor  = lane & 7;
    const int bsel  = (lane >> 3) & 1;

    float acc[2][4][4];
#pragma unroll
    for (int im = 0; im < 2; im++)
#pragma unroll
        for (int j = 0; j < 4; j++)
#pragma unroll
            for (int c = 0; c < 4; c++) acc[im][j][c] = 0.f;

    float rF[16];     // raw fp32 A (loaded iter i, converted end of iter i)
    uint2 rH[4];      // packed fp16 A (STS'd top of iter i+1)

    auto ldgF = [&](int k, int a0) {
        const float* p = A + ((size_t)k*1024 + s0 + rowgrp)*512 + a0 + lane16*4;
#pragma unroll
        for (int jj = 0; jj < 4; jj++) {
            float4 v = *reinterpret_cast<const float4*>(p + (size_t)jj * 16 * 512);
            rF[4*jj+0] = v.x; rF[4*jj+1] = v.y; rF[4*jj+2] = v.z; rF[4*jj+3] = v.w;
        }
    };
    auto cvtA = [&]() {
#pragma unroll
        for (int jj = 0; jj < 4; jj++)
            rH[jj] = make_uint2(packh(rF[4*jj+0], rF[4*jj+1]),
                                packh(rF[4*jj+2], rF[4*jj+3]));
    };
    auto stsA = [&](int buf) {
        const int unit = lane16 >> 1;
        const int sub  = (lane16 & 1) * 8;
#pragma unroll
        for (int jj = 0; jj < 4; jj++) {
            const int row = rowgrp + 16*jj;
            *reinterpret_cast<uint2*>(smem + buf*ATILE + row*128 +
                                      ((unit ^ (row & 7)) << 4) + sub) = rH[jj];
        }
    };
    auto cpB = [&](int k, int a0, int buf) {
        const __half* src = g_Uf + (size_t)(brow + 128 - k)*512 + a0;
        const uint32_t dst = smb + BOFF0 + buf*BTILE + brow*128;
        const int rx = brow & 7;
#pragma unroll
        for (int c = 0; c < 4; c++) {
            const int u = bhalf*4 + c;
            cpa16(dst + ((u ^ rx) << 4), src + u*8);
        }
    };

    // ---- prologue ----
    {
        int k0, a00, k1, a01;
        kofit(0, k0, a00);
        kofit(1, k1, a01);
        cpB(k0, a00, 0); asm volatile("cp.async.commit_group;" ::: "memory");
        cpB(k1, a01, 1); asm volatile("cp.async.commit_group;" ::: "memory");
        ldgF(k0, a00); cvtA(); stsA(0);
        ldgF(k1, a01); cvtA();
    }

    // ---- main loop (NIT iterations, K=64 each) ----
    for (int i = 0; i < NIT; i++) {
        const int abuf = i & 1;
        const int bbuf = i % 3;
        int k, a0dummy; kofit(i, k, a0dummy);

        if (i < NIT-1) asm volatile("cp.async.wait_group 1;" ::: "memory");
        else           asm volatile("cp.async.wait_group 0;" ::: "memory");
        __syncthreads();

        if (i + 1 < NIT) stsA((i + 1) & 1);
        if (i + 2 < NIT) {
            int kn, a0n; kofit(i + 2, kn, a0n);
            ldgF(kn, a0n);
            cpB(kn, a0n, (i + 2) % 3);
            asm volatile("cp.async.commit_group;" ::: "memory");
        }

        // causal liveness: n8-tile j covers n in [(4j+ng)*8, +8)
        bool lv[4];
#pragma unroll
        for (int j = 0; j < 4; j++)
            lv[j] = (k < ((4*j + ng) << 3) + 8);
        bool lp[2];
#pragma unroll
        for (int p = 0; p < 2; p++)
            lp[p] = lv[2*p + 1];      // lv monotone increasing in j

        const uint32_t ab = smb + abuf*ATILE + arow*128;
        const uint32_t bb = smb + BOFF0 + bbuf*BTILE + browl*128;
#pragma unroll
        for (int kb = 0; kb < 4; kb++) {
            uint32_t ah[2][4], uf[2][4];
            const int au = 2*kb + asel;
            ldmx4(ah[0], ab +        ((au ^ axor) << 4));
            ldmx4(ah[1], ab + 2048 + ((au ^ axor) << 4));
            const int bu = 2*kb + bsel;
            const uint32_t bsw = (uint32_t)((bu ^ bxor) << 4);
#pragma unroll
            for (int p = 0; p < 2; p++)
                if (lp[p]) ldmx4(uf[p], bb + p*8192 + bsw);
#pragma unroll
            for (int im = 0; im < 2; im++)
#pragma unroll
                for (int j = 0; j < 4; j++)
                    if (lv[j])
                        mma16816(acc[im][j], ah[im], &uf[j >> 1][(j & 1) * 2]);
        }

        if (i + 2 < NIT) cvtA();
    }

    // ---- epilogue: write split-K partials [g][t][s] ----
    float* pb = g_partial + (size_t)g * 131072;
    const int sidx = s0 + wm*32 + (lane >> 2);
#pragma unroll
    for (int im = 0; im < 2; im++) {
        const int sr = sidx + im*16;
#pragma unroll
        for (int j = 0; j < 4; j++) {
            const int n = ((4*j + ng) << 3) + (lane & 3) * 2;
            pb[(size_t)n      * 1024 + sr]     = acc[im][j][0];
            pb[(size_t)(n+1)  * 1024 + sr]     = acc[im][j][1];
            pb[(size_t)n      * 1024 + sr + 8] = acc[im][j][2];
            pb[(size_t)(n+1)  * 1024 + sr + 8] = acc[im][j][3];
        }
    }
}

__global__ __launch_bounds__(256) void reduce_kernel(float* __restrict__ out)
{
    int i = blockIdx.x*256 + threadIdx.x;    // 0..32767 float4s
    float4 s = make_float4(0.f, 0.f, 0.f, 0.f);
#pragma unroll
    for (int gg = 0; gg < KSPLIT; gg++) {
        float4 v = *reinterpret_cast<const float4*>(
            g_partial + (size_t)gg*131072 + (size_t)i*4);
        s.x += v.x; s.y += v.y; s.z += v.z; s.w += v.w;
    }
    reinterpret_cast<float4*>(out)[i] = s;
}

extern "C" void kernel_launch(void* const* d_in, const int* in_sizes, int n_in,
                              void* d_out, int out_size)
{
    const float* us = (const float*)d_in[0];   // [128, 512]
    const float* A  = (const float*)d_in[1];   // [128, 1024, 512]
    if (n_in >= 2 && in_sizes[0] > in_sizes[1]) {
        const float* t = us; us = A; A = t;
    }
    cudaFuncSetAttribute(mma_kernel, cudaFuncAttributeMaxDynamicSharedMemorySize, SMEMT);

    prep_kernel<<<512, 256>>>(us);
    dummy_kernel<<<1, 1>>>();
    dummy_kernel<<<1, 1>>>();
    mma_kernel<<<dim3(16, KSPLIT), 256, SMEMT>>>(A);
    reduce_kernel<<<128, 256>>>((float*)d_out);
}

// round 17
// speedup vs baseline: 1.6169x; 1.0395x over previous
#include <cuda_runtime.h>
#include <cuda_fp16.h>
#include <cstdint>

// out[t,s] = sum_{k<=t} sum_a A[k,s,a] * us[t-k,a]
// GEMM: C[s,t] = sum_{k,a} A[k,s,a] * Upad[t+128-k, a]
// mma.sync.m16n8k16, single fp16 chain (rel_err ~2.7e-4 measured).
// R17: K=128 per barrier epoch. R16 profile: tensor 34%, issue 31%,
// ~1100 cyc/iter unattributed fixed cost scaling with iteration count
// (R8->R9's identical lever gave the session's biggest win). Epoch =
// reflected k-pair (p, 127-p) at one a-chunk: causal liveness sums to
// ~1.06 live n-tiles per pair -> MMA work per epoch == two R16 iters,
// fixed costs halved (28-29 epochs vs 57 iters).
// Stage = A(k0)+A(k1) 16KB + B(k0)+B(k1) 32KB, double-buffered 96KB
// (occ-2 cap 114KB). A LDG k0 before ks0 MMA block, k1 before ks1
// (latency covered by half-body); rF[16] staging reused. Geometry,
// fragments, per-(n,s) accumulation order unchanged from R16.
// Occ 2, 16 s-tiles x KSPLIT=18 = 288 CTAs, CTA 64m x 128n, 8 warps
// (2m x 4n interleaved n8, SMSP-balanced ng), causal skip on MMA +
// B ldmatrix, XOR-swizzled 128B rows, deterministic split-K + reduce.
// Dummies keep ncu's capture slot on mma_kernel.

#define KSPLIT 18
#define ATILE  8192            // one A tile: 64 rows x 128 B
#define ASTG   (2*ATILE)       // A(k0)+A(k1) per stage
#define BTILE  16384           // one B tile: 128 rows x 128 B
#define BSTG   (2*BTILE)       // B(k0)+B(k1) per stage
#define BOFF0  (2*ASTG)        // B region after 2 A stages
#define SMEMT  (2*ASTG + 2*BSTG)     // 98304 B

__device__ float  g_partial[KSPLIT*128*1024];  // 9.4 MB
__device__ __half g_Uf[256*512];

__global__ __launch_bounds__(256) void prep_kernel(const float* __restrict__ us)
{
    int i = blockIdx.x*256 + threadIdx.x;   // 0..131071 over [256][512]
    int r = i >> 9, a = i & 511;
    float x = (r >= 128) ? us[(r-128)*512 + a] : 0.f;
    g_Uf[i] = __float2half_rn(x);
}

__global__ void dummy_kernel() {}

__device__ __forceinline__ void ldmx4(uint32_t* r, uint32_t addr) {
    asm volatile("ldmatrix.sync.aligned.m8n8.x4.shared.b16 {%0,%1,%2,%3}, [%4];"
        : "=r"(r[0]), "=r"(r[1]), "=r"(r[2]), "=r"(r[3]) : "r"(addr));
}
__device__ __forceinline__ void mma16816(float* c, const uint32_t* a, const uint32_t* b) {
    asm volatile("mma.sync.aligned.m16n8k16.row.col.f32.f16.f16.f32 "
        "{%0,%1,%2,%3}, {%4,%5,%6,%7}, {%8,%9}, {%0,%1,%2,%3};"
        : "+f"(c[0]), "+f"(c[1]), "+f"(c[2]), "+f"(c[3])
        : "r"(a[0]), "r"(a[1]), "r"(a[2]), "r"(a[3]), "r"(b[0]), "r"(b[1]));
}
__device__ __forceinline__ void cpa16(uint32_t dst, const void* src) {
    asm volatile("cp.async.cg.shared.global [%0], [%1], 16;" :: "r"(dst), "l"(src));
}
__device__ __forceinline__ uint32_t packh(float a, float b) {
    __half2 h = __floats2half2_rn(a, b);
    return *reinterpret_cast<uint32_t*>(&h);
}

__global__ __launch_bounds__(256, 2)
void mma_kernel(const float* __restrict__ A)
{
    extern __shared__ char smem[];
    const uint32_t smb = (uint32_t)__cvta_generic_to_shared(smem);

    const int tid  = threadIdx.x;
    const int wid  = tid >> 5;
    const int lane = tid & 31;
    const int wm   = wid >> 2;                     // 2 m-groups of 32
    const int ng   = (wid < 4) ? wid : 7 - wid;    // SMSP-balanced n-group
    const int s0   = blockIdx.x * 64;
    const int g    = blockIdx.y;

    // epoch quanta: q2 in [0,512) per s-tile; p=q2>>3, a0=(q2&7)<<6,
    // k0=p, k1=127-p  (pair live cost ~constant -> balanced CTAs)
    const int qs2 = (g * 512) / KSPLIT;
    const int qe2 = ((g + 1) * 512) / KSPLIT;
    const int NE  = qe2 - qs2;                     // 28 or 29

    auto kofe = [&](int e, int& k0, int& k1, int& a0) {
        const int q = qs2 + e;
        const int p = q >> 3;
        k0 = p; k1 = 127 - p;
        a0 = (q & 7) << 6;
    };

    // A loader: 16 threads/row, rows rowgrp+16*jj (jj 0..3)
    const int rowgrp = tid >> 4;        // 0..15
    const int lane16 = tid & 15;
    // B loader: 2 threads per row
    const int brow  = tid >> 1;         // 0..127
    const int bhalf = tid & 1;

    // ldmatrix geometry (16B-unit XOR swizzle on 128B rows)
    const int arow  = wm*32 + (lane & 15);                        // 0..63
    const int axor  = arow & 7;
    const int asel  = lane >> 4;
    const int browl = 8*ng + (lane & 7) + 32*((lane >> 4) & 1);   // 0..127
    const int bxor  = lane & 7;
    const int bsel  = (lane >> 3) & 1;

    float acc[2][4][4];
#pragma unroll
    for (int im = 0; im < 2; im++)
#pragma unroll
        for (int j = 0; j < 4; j++)
#pragma unroll
            for (int c = 0; c < 4; c++) acc[im][j][c] = 0.f;

    float rF[16];     // fp32 A staging, reused for both k halves

    auto ldgF = [&](int k, int a0) {
        const float* p = A + ((size_t)k*1024 + s0 + rowgrp)*512 + a0 + lane16*4;
#pragma unroll
        for (int jj = 0; jj < 4; jj++) {
            float4 v = *reinterpret_cast<const float4*>(p + (size_t)jj * 16 * 512);
            rF[4*jj+0] = v.x; rF[4*jj+1] = v.y; rF[4*jj+2] = v.z; rF[4*jj+3] = v.w;
        }
    };
    auto cvtstsA = [&](int buf, int ks) {
        const int unit = lane16 >> 1;
        const int sub  = (lane16 & 1) * 8;
        char* base = smem + buf*ASTG + ks*ATILE;
#pragma unroll
        for (int jj = 0; jj < 4; jj++) {
            const int row = rowgrp + 16*jj;
            uint2 hv = make_uint2(packh(rF[4*jj+0], rF[4*jj+1]),
                                  packh(rF[4*jj+2], rF[4*jj+3]));
            *reinterpret_cast<uint2*>(base + row*128 +
                                      ((unit ^ (row & 7)) << 4) + sub) = hv;
        }
    };
    auto cpB = [&](int k, int a0, int buf, int ks) {
        const __half* src = g_Uf + (size_t)(brow + 128 - k)*512 + a0;
        const uint32_t dst = smb + BOFF0 + buf*BSTG + ks*BTILE + brow*128;
        const int rx = brow & 7;
#pragma unroll
        for (int c = 0; c < 4; c++) {
            const int u = bhalf*4 + c;
            cpa16(dst + ((u ^ rx) << 4), src + u*8);
        }
    };

    // one ks-half of the MMA body
    auto half_body = [&](int buf, int ks, int k) {
        bool lv[4];
#pragma unroll
        for (int j = 0; j < 4; j++)
            lv[j] = (k < ((4*j + ng) << 3) + 8);
        bool lp[2];
#pragma unroll
        for (int p = 0; p < 2; p++)
            lp[p] = lv[2*p + 1];          // lv monotone increasing in j

        const uint32_t ab = smb + buf*ASTG + ks*ATILE + arow*128;
        const uint32_t bb = smb + BOFF0 + buf*BSTG + ks*BTILE + browl*128;
#pragma unroll
        for (int kb = 0; kb < 4; kb++) {
            uint32_t ah[2][4], uf[2][4];
            const int au = 2*kb + asel;
            ldmx4(ah[0], ab +        ((au ^ axor) << 4));
            ldmx4(ah[1], ab + 2048 + ((au ^ axor) << 4));
            const int bu = 2*kb + bsel;
            const uint32_t bsw = (uint32_t)((bu ^ bxor) << 4);
#pragma unroll
            for (int p = 0; p < 2; p++)
                if (lp[p]) ldmx4(uf[p], bb + p*8192 + bsw);
#pragma unroll
            for (int im = 0; im < 2; im++)
#pragma unroll
                for (int j = 0; j < 4; j++)
                    if (lv[j])
                        mma16816(acc[im][j], ah[im], &uf[j >> 1][(j & 1) * 2]);
        }
    };

    // ---- prologue: stage epoch 0 ----
    {
        int k0, k1, a0; kofe(0, k0, k1, a0);
        cpB(k0, a0, 0, 0);
        cpB(k1, a0, 0, 1);
        asm volatile("cp.async.commit_group;" ::: "memory");
        ldgF(k0, a0); cvtstsA(0, 0);
        ldgF(k1, a0); cvtstsA(0, 1);
    }

    // ---- main loop (NE epochs, K=128 each) ----
    for (int e = 0; e < NE; e++) {
        const int buf = e & 1;
        int k0, k1, a0; kofe(e, k0, k1, a0);

        asm volatile("cp.async.wait_group 0;" ::: "memory");
        __syncthreads();

        int k0n = 0, k1n = 0, a0n = 0;
        const bool more = (e + 1 < NE);
        if (more) {
            kofe(e + 1, k0n, k1n, a0n);
            cpB(k0n, a0n, buf ^ 1, 0);
            cpB(k1n, a0n, buf ^ 1, 1);
            asm volatile("cp.async.commit_group;" ::: "memory");
            ldgF(k0n, a0n);                 // consumed after ks0 block
        }

        half_body(buf, 0, k0);

        if (more) {
            cvtstsA(buf ^ 1, 0);
            ldgF(k1n, a0n);                 // consumed after ks1 block
        }

        half_body(buf, 1, k1);

        if (more) cvtstsA(buf ^ 1, 1);
    }

    // ---- epilogue: write split-K partials [g][t][s] ----
    float* pb = g_partial + (size_t)g * 131072;
    const int sidx = s0 + wm*32 + (lane >> 2);
#pragma unroll
    for (int im = 0; im < 2; im++) {
        const int sr = sidx + im*16;
#pragma unroll
        for (int j = 0; j < 4; j++) {
            const int n = ((4*j + ng) << 3) + (lane & 3) * 2;
            pb[(size_t)n      * 1024 + sr]     = acc[im][j][0];
            pb[(size_t)(n+1)  * 1024 + sr]     = acc[im][j][1];
            pb[(size_t)n      * 1024 + sr + 8] = acc[im][j][2];
            pb[(size_t)(n+1)  * 1024 + sr + 8] = acc[im][j][3];
        }
    }
}

__global__ __launch_bounds__(256) void reduce_kernel(float* __restrict__ out)
{
    int i = blockIdx.x*256 + threadIdx.x;    // 0..32767 float4s
    float4 s = make_float4(0.f, 0.f, 0.f, 0.f);
#pragma unroll
    for (int gg = 0; gg < KSPLIT; gg++) {
        float4 v = *reinterpret_cast<const float4*>(
            g_partial + (size_t)gg*131072 + (size_t)i*4);
        s.x += v.x; s.y += v.y; s.z += v.z; s.w += v.w;
    }
    reinterpret_cast<float4*>(out)[i] = s;
}

extern "C" void kernel_launch(void* const* d_in, const int* in_sizes, int n_in,
                              void* d_out, int out_size)
{
    const float* us = (const float*)d_in[0];   // [128, 512]
    const float* A  = (const float*)d_in[1];   // [128, 1024, 512]
    if (n_in >= 2 && in_sizes[0] > in_sizes[1]) {
        const float* t = us; us = A; A = t;
    }
    cudaFuncSetAttribute(mma_kernel, cudaFuncAttributeMaxDynamicSharedMemorySize, SMEMT);

    prep_kernel<<<512, 256>>>(us);
    dummy_kernel<<<1, 1>>>();
    dummy_kernel<<<1, 1>>>();
    mma_kernel<<<dim3(16, KSPLIT), 256, SMEMT>>>(A);
    reduce_kernel<<<128, 256>>>((float*)d_out);
}